// round 5
// baseline (speedup 1.0000x reference)
#include <cuda_runtime.h>

#define D_CH 20
#define GV 128
#define NUM_EMB (GV * GV * GV)
#define NUM_BINS (GV * GV)          // key = gz*128 + gy
#define REP 8                        // counter replicas per bin (contention fix)
#define NUM_CTR (NUM_BINS * REP)     // 131072 counters
#define MAXP (1 << 21)

__device__ int    g_hist[NUM_CTR];
__device__ int    g_cursor[NUM_CTR];
__device__ float4 g_sorted[MAXP];

__device__ __forceinline__ int bin_key(float py, float pz)
{
    int gy = (int)floorf((py + 1.0f) * 0.5f * (float)GV);
    int gz = (int)floorf((pz + 1.0f) * 0.5f * (float)GV);
    gy = min(max(gy, 0), GV - 1);
    gz = min(max(gz, 0), GV - 1);
    return gz * GV + gy;
}

__global__ void zero_hist_kernel()
{
    int i = blockIdx.x * blockDim.x + threadIdx.x;
    if (i < NUM_CTR) g_hist[i] = 0;
}

__global__ void hist_kernel(const float* __restrict__ x, int n)
{
    int p = blockIdx.x * blockDim.x + threadIdx.x;
    if (p >= n) return;
    float py = __ldg(&x[p * 3 + 1]);
    float pz = __ldg(&x[p * 3 + 2]);
    int ctr = bin_key(py, pz) * REP + (p & (REP - 1));
    atomicAdd(&g_hist[ctr], 1);          // no return use -> RED
}

// Single-block exclusive scan over NUM_CTR = 131072 (1024 threads x 128 each).
// Two sequential reads of g_hist per thread (can't hold 128 in regs).
__global__ void scan_kernel()
{
    __shared__ int sh[1024];
    const int tid = threadIdx.x;
    const int PER = NUM_CTR / 1024;      // 128

    int tot = 0;
    for (int i = 0; i < PER; i++)
        tot += g_hist[tid * PER + i];
    sh[tid] = tot;
    __syncthreads();

    // Hillis-Steele inclusive scan on 1024 totals
    for (int off = 1; off < 1024; off <<= 1) {
        int v = sh[tid];
        int add = (tid >= off) ? sh[tid - off] : 0;
        __syncthreads();
        sh[tid] = v + add;
        __syncthreads();
    }

    int running = (tid == 0) ? 0 : sh[tid - 1];   // exclusive prefix
    for (int i = 0; i < PER; i++) {
        int c = g_hist[tid * PER + i];
        g_cursor[tid * PER + i] = running;
        running += c;
    }
}

__global__ void scatter_kernel(const float* __restrict__ x, int n)
{
    int p = blockIdx.x * blockDim.x + threadIdx.x;
    if (p >= n) return;
    float px = __ldg(&x[p * 3 + 0]);
    float py = __ldg(&x[p * 3 + 1]);
    float pz = __ldg(&x[p * 3 + 2]);
    int ctr = bin_key(py, pz) * REP + (p & (REP - 1));
    int pos = atomicAdd(&g_cursor[ctr], 1);
    __stcs(&g_sorted[pos], make_float4(px, py, pz, __int_as_float(p)));
}

__global__ void __launch_bounds__(256) gather_kernel(
    const float* __restrict__ grid,
    float* __restrict__ out,
    int n_pts)
{
    unsigned int gid = blockIdx.x * 256u + threadIdx.x;
    unsigned int total = (unsigned int)n_pts * 5u;   // 5 threads/point, 4 channels
    if (gid >= total) return;

    unsigned int sp = gid / 5u;
    unsigned int c4 = gid - sp * 5u;
    unsigned int cbase = c4 * 4u;

    // Read-once stream: don't evict grid strips from L2.
    float4 pt = __ldcs(&g_sorted[sp]);
    float px = pt.x, py = pt.y, pz = pt.z;
    int orig = __float_as_int(pt.w);

    float tx = (px + 1.0f) * 0.5f * (float)GV;
    float ty = (py + 1.0f) * 0.5f * (float)GV;
    float tz = (pz + 1.0f) * 0.5f * (float)GV;
    int gx = (int)floorf(tx);
    int gy = (int)floorf(ty);
    int gz = (int)floorf(tz);

    const float inv_v2 = 2.0f / (float)GV;   // exact in fp32
    float x1 = (float)gx * inv_v2 - 1.0f;
    float x2 = (float)(gx + 1) * inv_v2 - 1.0f;
    float y1 = (float)gy * inv_v2 - 1.0f;
    float y2 = (float)(gy + 1) * inv_v2 - 1.0f;
    float z1 = (float)gz * inv_v2 - 1.0f;
    float z2 = (float)(gz + 1) * inv_v2 - 1.0f;

    const float inv_den = 64.0f;             // 1/(2/128), exact
    float wx0 = (x2 - px) * inv_den;
    float wx1 = (px - x1) * inv_den;
    float wy0 = (y2 - py) * inv_den;
    float wy1 = (py - y1) * inv_den;
    float wz0 = (z2 - pz) * inv_den;
    float wz1 = (pz - z1) * inv_den;

    int base = gx + gy * GV + gz * GV * GV;
    const int maxi = NUM_EMB - 1;
    int f000 = min(base,                  maxi);
    int f100 = min(base + 1,              maxi);
    int f010 = min(base + GV,             maxi);
    int f110 = min(base + GV + 1,         maxi);
    int f001 = min(base + GV*GV,          maxi);
    int f101 = min(base + GV*GV + 1,      maxi);
    int f011 = min(base + GV*GV + GV,     maxi);
    int f111 = min(base + GV*GV + GV + 1, maxi);

    const float4* g4 = (const float4*)grid;
    float4 q000 = __ldg(&g4[((size_t)f000 * D_CH + cbase) >> 2]);
    float4 q100 = __ldg(&g4[((size_t)f100 * D_CH + cbase) >> 2]);
    float4 q010 = __ldg(&g4[((size_t)f010 * D_CH + cbase) >> 2]);
    float4 q110 = __ldg(&g4[((size_t)f110 * D_CH + cbase) >> 2]);
    float4 q001 = __ldg(&g4[((size_t)f001 * D_CH + cbase) >> 2]);
    float4 q101 = __ldg(&g4[((size_t)f101 * D_CH + cbase) >> 2]);
    float4 q011 = __ldg(&g4[((size_t)f011 * D_CH + cbase) >> 2]);
    float4 q111 = __ldg(&g4[((size_t)f111 * D_CH + cbase) >> 2]);

    float4 r;
    {
        float fx0 = wx0 * q000.x + wx1 * q100.x;
        float fx1 = wx0 * q010.x + wx1 * q110.x;
        float fx2 = wx0 * q001.x + wx1 * q101.x;
        float fx3 = wx0 * q011.x + wx1 * q111.x;
        r.x = wz0 * (wy0 * fx0 + wy1 * fx1) + wz1 * (wy0 * fx2 + wy1 * fx3);
    }
    {
        float fx0 = wx0 * q000.y + wx1 * q100.y;
        float fx1 = wx0 * q010.y + wx1 * q110.y;
        float fx2 = wx0 * q001.y + wx1 * q101.y;
        float fx3 = wx0 * q011.y + wx1 * q111.y;
        r.y = wz0 * (wy0 * fx0 + wy1 * fx1) + wz1 * (wy0 * fx2 + wy1 * fx3);
    }
    {
        float fx0 = wx0 * q000.z + wx1 * q100.z;
        float fx1 = wx0 * q010.z + wx1 * q110.z;
        float fx2 = wx0 * q001.z + wx1 * q101.z;
        float fx3 = wx0 * q011.z + wx1 * q111.z;
        r.z = wz0 * (wy0 * fx0 + wy1 * fx1) + wz1 * (wy0 * fx2 + wy1 * fx3);
    }
    {
        float fx0 = wx0 * q000.w + wx1 * q100.w;
        float fx1 = wx0 * q010.w + wx1 * q110.w;
        float fx2 = wx0 * q001.w + wx1 * q101.w;
        float fx3 = wx0 * q011.w + wx1 * q111.w;
        r.w = wz0 * (wy0 * fx0 + wy1 * fx1) + wz1 * (wy0 * fx2 + wy1 * fx3);
    }

    // Output goes to the point's ORIGINAL slot: scattered but 80B-contiguous.
    __stcs((float4*)out + (size_t)orig * 5u + c4, r);
}

// Fallback (unsorted) path if n_pts exceeds static scratch capacity.
__global__ void __launch_bounds__(256) gather_direct_kernel(
    const float* __restrict__ x,
    const float* __restrict__ grid,
    float* __restrict__ out,
    int n_pts)
{
    unsigned int gid = blockIdx.x * 256u + threadIdx.x;
    unsigned int total = (unsigned int)n_pts * 5u;
    if (gid >= total) return;
    unsigned int p = gid / 5u;
    unsigned int c4 = gid - p * 5u;
    unsigned int cbase = c4 * 4u;

    float px = __ldg(&x[p * 3 + 0]);
    float py = __ldg(&x[p * 3 + 1]);
    float pz = __ldg(&x[p * 3 + 2]);
    float tx = (px + 1.0f) * 0.5f * (float)GV;
    float ty = (py + 1.0f) * 0.5f * (float)GV;
    float tz = (pz + 1.0f) * 0.5f * (float)GV;
    int gx = (int)floorf(tx), gy = (int)floorf(ty), gz = (int)floorf(tz);
    const float inv_v2 = 2.0f / (float)GV;
    float x1 = (float)gx * inv_v2 - 1.0f, x2 = (float)(gx+1) * inv_v2 - 1.0f;
    float y1 = (float)gy * inv_v2 - 1.0f, y2 = (float)(gy+1) * inv_v2 - 1.0f;
    float z1 = (float)gz * inv_v2 - 1.0f, z2 = (float)(gz+1) * inv_v2 - 1.0f;
    const float inv_den = 64.0f;
    float wx0 = (x2-px)*inv_den, wx1 = (px-x1)*inv_den;
    float wy0 = (y2-py)*inv_den, wy1 = (py-y1)*inv_den;
    float wz0 = (z2-pz)*inv_den, wz1 = (pz-z1)*inv_den;
    int base = gx + gy*GV + gz*GV*GV;
    const int maxi = NUM_EMB - 1;
    int f[8] = { min(base,maxi), min(base+1,maxi), min(base+GV,maxi), min(base+GV+1,maxi),
                 min(base+GV*GV,maxi), min(base+GV*GV+1,maxi),
                 min(base+GV*GV+GV,maxi), min(base+GV*GV+GV+1,maxi) };
    const float4* g4 = (const float4*)grid;
    float4 q[8];
    #pragma unroll
    for (int i = 0; i < 8; i++) q[i] = __ldg(&g4[((size_t)f[i] * D_CH + cbase) >> 2]);
    float4 r;
    float fx0, fx1, fx2, fx3;
    fx0 = wx0*q[0].x + wx1*q[1].x; fx1 = wx0*q[2].x + wx1*q[3].x;
    fx2 = wx0*q[4].x + wx1*q[5].x; fx3 = wx0*q[6].x + wx1*q[7].x;
    r.x = wz0*(wy0*fx0 + wy1*fx1) + wz1*(wy0*fx2 + wy1*fx3);
    fx0 = wx0*q[0].y + wx1*q[1].y; fx1 = wx0*q[2].y + wx1*q[3].y;
    fx2 = wx0*q[4].y + wx1*q[5].y; fx3 = wx0*q[6].y + wx1*q[7].y;
    r.y = wz0*(wy0*fx0 + wy1*fx1) + wz1*(wy0*fx2 + wy1*fx3);
    fx0 = wx0*q[0].z + wx1*q[1].z; fx1 = wx0*q[2].z + wx1*q[3].z;
    fx2 = wx0*q[4].z + wx1*q[5].z; fx3 = wx0*q[6].z + wx1*q[7].z;
    r.z = wz0*(wy0*fx0 + wy1*fx1) + wz1*(wy0*fx2 + wy1*fx3);
    fx0 = wx0*q[0].w + wx1*q[1].w; fx1 = wx0*q[2].w + wx1*q[3].w;
    fx2 = wx0*q[4].w + wx1*q[5].w; fx3 = wx0*q[6].w + wx1*q[7].w;
    r.w = wz0*(wy0*fx0 + wy1*fx1) + wz1*(wy0*fx2 + wy1*fx3);
    __stcs((float4*)out + gid, r);
}

extern "C" void kernel_launch(void* const* d_in, const int* in_sizes, int n_in,
                              void* d_out, int out_size)
{
    const float* x    = (const float*)d_in[0];
    const float* grid = (const float*)d_in[1];
    float* out        = (float*)d_out;

    int n_pts = in_sizes[0] / 3;

    if (n_pts > MAXP) {
        unsigned int total = (unsigned int)n_pts * 5u;
        gather_direct_kernel<<<(total + 255u) / 256u, 256>>>(x, grid, out, n_pts);
        return;
    }

    int pb = (n_pts + 255) / 256;
    unsigned int total = (unsigned int)n_pts * 5u;

    zero_hist_kernel<<<(NUM_CTR + 1023) / 1024, 1024>>>();
    hist_kernel<<<pb, 256>>>(x, n_pts);
    scan_kernel<<<1, 1024>>>();
    scatter_kernel<<<pb, 256>>>(x, n_pts);
    gather_kernel<<<(total + 255u) / 256u, 256>>>(grid, out, n_pts);
}

// round 6
// speedup vs baseline: 2.7597x; 2.7597x over previous
#include <cuda_runtime.h>

#define D_CH 20
#define GV 128
#define NUM_EMB (GV * GV * GV)
#define NUM_BINS (GV * GV)      // key = gz*128 + gy
#define MAXP (1 << 21)

__device__ int    g_hist[NUM_BINS];     // bin counts (atomic pass)
__device__ int    g_base[NUM_BINS];     // exclusive-scan bases
__device__ int    g_rank[MAXP];         // per-point rank within its bin
__device__ float4 g_sorted[MAXP];

__device__ __forceinline__ int bin_key(float py, float pz)
{
    int gy = (int)floorf((py + 1.0f) * 0.5f * (float)GV);
    int gz = (int)floorf((pz + 1.0f) * 0.5f * (float)GV);
    gy = min(max(gy, 0), GV - 1);
    gz = min(max(gz, 0), GV - 1);
    return gz * GV + gy;
}

__global__ void zero_hist_kernel()
{
    int i = blockIdx.x * blockDim.x + threadIdx.x;
    if (i < NUM_BINS) g_hist[i] = 0;
}

// One atomic pass: count AND record each point's rank within its bin.
__global__ void hist_rank_kernel(const float* __restrict__ x, int n)
{
    int p = blockIdx.x * blockDim.x + threadIdx.x;
    if (p >= n) return;
    float py = __ldg(&x[p * 3 + 1]);
    float pz = __ldg(&x[p * 3 + 2]);
    int ctr = bin_key(py, pz);
    int rank = atomicAdd(&g_hist[ctr], 1);
    __stcs(&g_rank[p], rank);
}

// Single-block exclusive scan over NUM_BINS=16384 (1024 threads x 16 each)
__global__ void scan_kernel()
{
    __shared__ int sh[1024];
    const int tid = threadIdx.x;
    const int PER = NUM_BINS / 1024;   // 16

    int loc[PER];
    int tot = 0;
    #pragma unroll
    for (int i = 0; i < PER; i++) {
        loc[i] = g_hist[tid * PER + i];
        tot += loc[i];
    }
    sh[tid] = tot;
    __syncthreads();

    #pragma unroll
    for (int off = 1; off < 1024; off <<= 1) {
        int v = sh[tid];
        int add = (tid >= off) ? sh[tid - off] : 0;
        __syncthreads();
        sh[tid] = v + add;
        __syncthreads();
    }

    int running = (tid == 0) ? 0 : sh[tid - 1];  // exclusive prefix
    #pragma unroll
    for (int i = 0; i < PER; i++) {
        g_base[tid * PER + i] = running;
        running += loc[i];
    }
}

// Atomic-free scatter: pos = base[bin] + rank[p]
__global__ void scatter_kernel(const float* __restrict__ x, int n)
{
    int p = blockIdx.x * blockDim.x + threadIdx.x;
    if (p >= n) return;
    float px = __ldg(&x[p * 3 + 0]);
    float py = __ldg(&x[p * 3 + 1]);
    float pz = __ldg(&x[p * 3 + 2]);
    int ctr  = bin_key(py, pz);
    int pos  = __ldg(&g_base[ctr]) + __ldcs(&g_rank[p]);
    __stcs(&g_sorted[pos], make_float4(px, py, pz, __int_as_float(p)));
}

__global__ void __launch_bounds__(256) gather_kernel(
    const float* __restrict__ grid,
    float* __restrict__ out,
    int n_pts)
{
    unsigned int gid = blockIdx.x * 256u + threadIdx.x;
    unsigned int total = (unsigned int)n_pts * 5u;   // 5 threads/point, 4 channels
    if (gid >= total) return;

    unsigned int sp = gid / 5u;
    unsigned int c4 = gid - sp * 5u;
    unsigned int cbase = c4 * 4u;

    // Read-once stream: don't evict grid strips from L2.
    float4 pt = __ldcs(&g_sorted[sp]);
    float px = pt.x, py = pt.y, pz = pt.z;
    int orig = __float_as_int(pt.w);

    float tx = (px + 1.0f) * 0.5f * (float)GV;
    float ty = (py + 1.0f) * 0.5f * (float)GV;
    float tz = (pz + 1.0f) * 0.5f * (float)GV;
    int gx = (int)floorf(tx);
    int gy = (int)floorf(ty);
    int gz = (int)floorf(tz);

    const float inv_v2 = 2.0f / (float)GV;   // exact in fp32
    float x1 = (float)gx * inv_v2 - 1.0f;
    float x2 = (float)(gx + 1) * inv_v2 - 1.0f;
    float y1 = (float)gy * inv_v2 - 1.0f;
    float y2 = (float)(gy + 1) * inv_v2 - 1.0f;
    float z1 = (float)gz * inv_v2 - 1.0f;
    float z2 = (float)(gz + 1) * inv_v2 - 1.0f;

    const float inv_den = 64.0f;             // 1/(2/128), exact
    float wx0 = (x2 - px) * inv_den;
    float wx1 = (px - x1) * inv_den;
    float wy0 = (y2 - py) * inv_den;
    float wy1 = (py - y1) * inv_den;
    float wz0 = (z2 - pz) * inv_den;
    float wz1 = (pz - z1) * inv_den;

    int base = gx + gy * GV + gz * GV * GV;
    const int maxi = NUM_EMB - 1;
    int f000 = min(base,                  maxi);
    int f100 = min(base + 1,              maxi);
    int f010 = min(base + GV,             maxi);
    int f110 = min(base + GV + 1,         maxi);
    int f001 = min(base + GV*GV,          maxi);
    int f101 = min(base + GV*GV + 1,      maxi);
    int f011 = min(base + GV*GV + GV,     maxi);
    int f111 = min(base + GV*GV + GV + 1, maxi);

    const float4* g4 = (const float4*)grid;
    float4 q000 = __ldg(&g4[((size_t)f000 * D_CH + cbase) >> 2]);
    float4 q100 = __ldg(&g4[((size_t)f100 * D_CH + cbase) >> 2]);
    float4 q010 = __ldg(&g4[((size_t)f010 * D_CH + cbase) >> 2]);
    float4 q110 = __ldg(&g4[((size_t)f110 * D_CH + cbase) >> 2]);
    float4 q001 = __ldg(&g4[((size_t)f001 * D_CH + cbase) >> 2]);
    float4 q101 = __ldg(&g4[((size_t)f101 * D_CH + cbase) >> 2]);
    float4 q011 = __ldg(&g4[((size_t)f011 * D_CH + cbase) >> 2]);
    float4 q111 = __ldg(&g4[((size_t)f111 * D_CH + cbase) >> 2]);

    float4 r;
    {
        float fx0 = wx0 * q000.x + wx1 * q100.x;
        float fx1 = wx0 * q010.x + wx1 * q110.x;
        float fx2 = wx0 * q001.x + wx1 * q101.x;
        float fx3 = wx0 * q011.x + wx1 * q111.x;
        r.x = wz0 * (wy0 * fx0 + wy1 * fx1) + wz1 * (wy0 * fx2 + wy1 * fx3);
    }
    {
        float fx0 = wx0 * q000.y + wx1 * q100.y;
        float fx1 = wx0 * q010.y + wx1 * q110.y;
        float fx2 = wx0 * q001.y + wx1 * q101.y;
        float fx3 = wx0 * q011.y + wx1 * q111.y;
        r.y = wz0 * (wy0 * fx0 + wy1 * fx1) + wz1 * (wy0 * fx2 + wy1 * fx3);
    }
    {
        float fx0 = wx0 * q000.z + wx1 * q100.z;
        float fx1 = wx0 * q010.z + wx1 * q110.z;
        float fx2 = wx0 * q001.z + wx1 * q101.z;
        float fx3 = wx0 * q011.z + wx1 * q111.z;
        r.z = wz0 * (wy0 * fx0 + wy1 * fx1) + wz1 * (wy0 * fx2 + wy1 * fx3);
    }
    {
        float fx0 = wx0 * q000.w + wx1 * q100.w;
        float fx1 = wx0 * q010.w + wx1 * q110.w;
        float fx2 = wx0 * q001.w + wx1 * q101.w;
        float fx3 = wx0 * q011.w + wx1 * q111.w;
        r.w = wz0 * (wy0 * fx0 + wy1 * fx1) + wz1 * (wy0 * fx2 + wy1 * fx3);
    }

    // Output goes to the point's ORIGINAL slot: scattered but 80B-contiguous.
    __stcs((float4*)out + (size_t)orig * 5u + c4, r);
}

// Fallback (unsorted) path if n_pts exceeds static scratch capacity.
__global__ void __launch_bounds__(256) gather_direct_kernel(
    const float* __restrict__ x,
    const float* __restrict__ grid,
    float* __restrict__ out,
    int n_pts)
{
    unsigned int gid = blockIdx.x * 256u + threadIdx.x;
    unsigned int total = (unsigned int)n_pts * 5u;
    if (gid >= total) return;
    unsigned int p = gid / 5u;
    unsigned int c4 = gid - p * 5u;
    unsigned int cbase = c4 * 4u;

    float px = __ldg(&x[p * 3 + 0]);
    float py = __ldg(&x[p * 3 + 1]);
    float pz = __ldg(&x[p * 3 + 2]);
    float tx = (px + 1.0f) * 0.5f * (float)GV;
    float ty = (py + 1.0f) * 0.5f * (float)GV;
    float tz = (pz + 1.0f) * 0.5f * (float)GV;
    int gx = (int)floorf(tx), gy = (int)floorf(ty), gz = (int)floorf(tz);
    const float inv_v2 = 2.0f / (float)GV;
    float x1 = (float)gx * inv_v2 - 1.0f, x2 = (float)(gx+1) * inv_v2 - 1.0f;
    float y1 = (float)gy * inv_v2 - 1.0f, y2 = (float)(gy+1) * inv_v2 - 1.0f;
    float z1 = (float)gz * inv_v2 - 1.0f, z2 = (float)(gz+1) * inv_v2 - 1.0f;
    const float inv_den = 64.0f;
    float wx0 = (x2-px)*inv_den, wx1 = (px-x1)*inv_den;
    float wy0 = (y2-py)*inv_den, wy1 = (py-y1)*inv_den;
    float wz0 = (z2-pz)*inv_den, wz1 = (pz-z1)*inv_den;
    int base = gx + gy*GV + gz*GV*GV;
    const int maxi = NUM_EMB - 1;
    int f[8] = { min(base,maxi), min(base+1,maxi), min(base+GV,maxi), min(base+GV+1,maxi),
                 min(base+GV*GV,maxi), min(base+GV*GV+1,maxi),
                 min(base+GV*GV+GV,maxi), min(base+GV*GV+GV+1,maxi) };
    const float4* g4 = (const float4*)grid;
    float4 q[8];
    #pragma unroll
    for (int i = 0; i < 8; i++) q[i] = __ldg(&g4[((size_t)f[i] * D_CH + cbase) >> 2]);
    float4 r;
    float fx0, fx1, fx2, fx3;
    fx0 = wx0*q[0].x + wx1*q[1].x; fx1 = wx0*q[2].x + wx1*q[3].x;
    fx2 = wx0*q[4].x + wx1*q[5].x; fx3 = wx0*q[6].x + wx1*q[7].x;
    r.x = wz0*(wy0*fx0 + wy1*fx1) + wz1*(wy0*fx2 + wy1*fx3);
    fx0 = wx0*q[0].y + wx1*q[1].y; fx1 = wx0*q[2].y + wx1*q[3].y;
    fx2 = wx0*q[4].y + wx1*q[5].y; fx3 = wx0*q[6].y + wx1*q[7].y;
    r.y = wz0*(wy0*fx0 + wy1*fx1) + wz1*(wy0*fx2 + wy1*fx3);
    fx0 = wx0*q[0].z + wx1*q[1].z; fx1 = wx0*q[2].z + wx1*q[3].z;
    fx2 = wx0*q[4].z + wx1*q[5].z; fx3 = wx0*q[6].z + wx1*q[7].z;
    r.z = wz0*(wy0*fx0 + wy1*fx1) + wz1*(wy0*fx2 + wy1*fx3);
    fx0 = wx0*q[0].w + wx1*q[1].w; fx1 = wx0*q[2].w + wx1*q[3].w;
    fx2 = wx0*q[4].w + wx1*q[5].w; fx3 = wx0*q[6].w + wx1*q[7].w;
    r.w = wz0*(wy0*fx0 + wy1*fx1) + wz1*(wy0*fx2 + wy1*fx3);
    __stcs((float4*)out + gid, r);
}

extern "C" void kernel_launch(void* const* d_in, const int* in_sizes, int n_in,
                              void* d_out, int out_size)
{
    const float* x    = (const float*)d_in[0];
    const float* grid = (const float*)d_in[1];
    float* out        = (float*)d_out;

    int n_pts = in_sizes[0] / 3;

    if (n_pts > MAXP) {
        unsigned int total = (unsigned int)n_pts * 5u;
        gather_direct_kernel<<<(total + 255u) / 256u, 256>>>(x, grid, out, n_pts);
        return;
    }

    int pb = (n_pts + 255) / 256;
    unsigned int total = (unsigned int)n_pts * 5u;

    zero_hist_kernel<<<(NUM_BINS + 1023) / 1024, 1024>>>();
    hist_rank_kernel<<<pb, 256>>>(x, n_pts);
    scan_kernel<<<1, 1024>>>();
    scatter_kernel<<<pb, 256>>>(x, n_pts);
    gather_kernel<<<(total + 255u) / 256u, 256>>>(grid, out, n_pts);
}